// round 5
// baseline (speedup 1.0000x reference)
#include <cuda_runtime.h>

#define NB 4096
#define L 64
#define D 128
#define TMAX 65            // counts are in [0, 64]
#define BPB 2              // batches per block (one per half-block)
#define GRID (NB / BPB)    // 2048 blocks
#define THREADS 256

// Lookup table: T[a][e] = sum_d relu(a*W1[d]+b1[d]) * W2[d][e] + b2[e]
__device__ float g_T[TMAX * D];

__global__ __launch_bounds__(D) void build_table_kernel(
    const float* __restrict__ W1, const float* __restrict__ b1,
    const float* __restrict__ W2, const float* __restrict__ b2)
{
    __shared__ float h[D];
    const int a = blockIdx.x;      // 0..64
    const int e = threadIdx.x;     // 0..127
    h[e] = fmaxf((float)a * W1[e] + b1[e], 0.0f);
    __syncthreads();
    float acc = b2[e];
    #pragma unroll 8
    for (int d = 0; d < D; ++d)
        acc = fmaf(h[d], W2[d * D + e], acc);
    g_T[a * D + e] = acc;
}

__global__ __launch_bounds__(THREADS) void nif_encoder_kernel(
    const int* __restrict__ src_ids, const int* __restrict__ dst_ids,
    const int* __restrict__ src_nb,  const int* __restrict__ dst_nb,
    float* __restrict__ out)
{
    __shared__ int s_srcL[BPB][L], s_dstL[BPB][L];
    __shared__ int s_cd[BPB], s_cs[BPB];
    __shared__ int s_a[BPB][2 * L];          // packed a0 | (a1<<8)

    const int tid  = threadIdx.x;
    const int lane = tid & 31;
    const int wrp  = tid >> 5;               // 0..7
    const int p    = tid >> 7;               // which batch of this block (0/1)
    const int h    = tid & 127;              // thread-in-batch
    const int base = blockIdx.x * BPB;
    const size_t half = (size_t)NB * L * D;

    if (tid < BPB) { s_cd[tid] = 0; s_cs[tid] = 0; }

    // ---- load both batches' neighbor lists (each half-block loads its own) ----
    const int b = base + p;
    if (h < L) s_srcL[p][h]     = __ldg(&src_nb[b * L + h]);
    else       s_dstL[p][h - L] = __ldg(&dst_nb[b * L + (h - L)]);

    // cache the two hot table rows while lists land (a=0 and a=1 cover ~97% of lookups)
    const float4* gT4 = (const float4*)g_T;   // [TMAX][32] float4
    const float4 t0r = __ldg(&gT4[0 * 32 + lane]);
    const float4 t1r = __ldg(&gT4[1 * 32 + lane]);
    __syncthreads();

    const int sid = __ldg(&src_ids[b]);
    const int did = __ldg(&dst_ids[b]);

    // ---- counts: each half-block does its own batch ----
    int c_self = 0, c_other = 0, my_x;
    if (h < L) {
        if (s_dstL[p][h] == sid) atomicAdd(&s_cd[p], 1);
        my_x = s_srcL[p][h];
        #pragma unroll
        for (int j = 0; j < L; ++j) {
            c_self  += (my_x == s_srcL[p][j]);
            c_other += (my_x == s_dstL[p][j]);
        }
    } else {
        const int i = h - L;
        if (s_srcL[p][i] == did) atomicAdd(&s_cs[p], 1);
        my_x = s_dstL[p][i];
        #pragma unroll
        for (int j = 0; j < L; ++j) {
            c_self  += (my_x == s_dstL[p][j]);
            c_other += (my_x == s_srcL[p][j]);
        }
    }
    __syncthreads();

    // ---- dict-mutation overrides (exact reference semantics) ----
    {
        const int  cd     = s_cd[p];
        const int  cs     = s_cs[p];
        const bool same   = (sid == did);
        const bool in_dst = (cd > 0);                      // srcid_in_dst
        const bool cond2  = (cs > 0) || (same && in_dst);
        const int  v2     = (same && in_dst) ? cd : cs;
        int a0, a1;
        if (h < L) {
            a0 = c_self;                                         // c_src
            a1 = (my_x == did && cond2)  ? v2 : c_other;         // src_col1
        } else {
            a0 = (my_x == sid && in_dst) ? cd : c_other;         // dst_col0
            a1 = c_self;                                         // c_dst
        }
        s_a[p][h] = a0 | (a1 << 8);
    }
    __syncthreads();

    // ---- barrier-free streaming store: 256 rows, one row per warp-iter ----
    // (a0,a1) is warp-uniform per row -> branches below are non-divergent.
    #pragma unroll 8
    for (int it = 0; it < 32; ++it) {
        const int g  = it * 8 + wrp;          // global row 0..255
        const int pp = g >> 7;                // batch within block
        const int r  = g & 127;               // row within batch
        const int packed = s_a[pp][r];
        const int a0 = packed & 0xFF;
        const int a1 = packed >> 8;

        float4 ta, tb;
        if (a0 == 1)      ta = t1r;
        else if (a0 == 0) ta = t0r;
        else              ta = __ldg(&gT4[a0 * 32 + lane]);
        if (a1 == 0)      tb = t0r;
        else if (a1 == 1) tb = t1r;
        else              tb = __ldg(&gT4[a1 * 32 + lane]);

        float4 o;
        o.x = ta.x + tb.x; o.y = ta.y + tb.y;
        o.z = ta.z + tb.z; o.w = ta.w + tb.w;
        const int bb = base + pp;
        float* dst_row = (r < L)
            ? (out + (size_t)bb * L * D + r * D)
            : (out + half + (size_t)bb * L * D + (r - L) * D);
        __stcs((float4*)&dst_row[lane * 4], o);
    }
}

extern "C" void kernel_launch(void* const* d_in, const int* in_sizes, int n_in,
                              void* d_out, int out_size)
{
    const int*   src_ids = (const int*)  d_in[0];
    const int*   dst_ids = (const int*)  d_in[1];
    const int*   src_nb  = (const int*)  d_in[2];
    const int*   dst_nb  = (const int*)  d_in[3];
    const float* W1      = (const float*)d_in[4];
    const float* b1      = (const float*)d_in[5];
    const float* W2      = (const float*)d_in[6];
    const float* b2      = (const float*)d_in[7];
    float*       out     = (float*)d_out;

    build_table_kernel<<<TMAX, D>>>(W1, b1, W2, b2);
    nif_encoder_kernel<<<GRID, THREADS>>>(src_ids, dst_ids, src_nb, dst_nb, out);
}

// round 6
// speedup vs baseline: 1.0374x; 1.0374x over previous
#include <cuda_runtime.h>

#define NB 4096
#define L 64
#define D 128
#define TMAX 65            // counts are in [0, 64]
#define NUM_IDS 1000
#define BPB 2              // batches per block (one per half-block)
#define GRID (NB / BPB)    // 2048 blocks
#define THREADS 256

// Lookup table: T[a][e] = sum_d relu(a*W1[d]+b1[d]) * W2[d][e] + b2[e]
__device__ float g_T[TMAX * D];

__global__ __launch_bounds__(D) void build_table_kernel(
    const float* __restrict__ W1, const float* __restrict__ b1,
    const float* __restrict__ W2, const float* __restrict__ b2)
{
    __shared__ float h[D];
    const int a = blockIdx.x;      // 0..64
    const int e = threadIdx.x;     // 0..127
    h[e] = fmaxf((float)a * W1[e] + b1[e], 0.0f);
    __syncthreads();
    float acc = b2[e];
    #pragma unroll 8
    for (int d = 0; d < D; ++d)
        acc = fmaf(h[d], W2[d * D + e], acc);
    g_T[a * D + e] = acc;
}

__global__ __launch_bounds__(THREADS) void nif_encoder_kernel(
    const int* __restrict__ src_ids, const int* __restrict__ dst_ids,
    const int* __restrict__ src_nb,  const int* __restrict__ dst_nb,
    float* __restrict__ out)
{
    // histogram counts per (batch, list): O(L) counting instead of O(L^2)
    __shared__ int s_cnt[BPB][2][NUM_IDS];       // 16 KB
    __shared__ int s_a[BPB][2 * L];              // packed a0 | (a1<<8)

    const int tid  = threadIdx.x;
    const int lane = tid & 31;
    const int wrp  = tid >> 5;               // 0..7
    const int p    = tid >> 7;               // which batch of this block (0/1)
    const int h    = tid & 127;              // thread-in-batch (one neighbor elem)
    const int base = blockIdx.x * BPB;
    const size_t half = (size_t)NB * L * D;
    const float4* gT4 = (const float4*)g_T;  // [TMAX][32] float4

    // ---- zero count arrays (1000 int4s across 256 threads) ----
    {
        int4* z = (int4*)&s_cnt[0][0][0];
        const int4 zero4 = make_int4(0, 0, 0, 0);
        #pragma unroll
        for (int i = tid; i < BPB * 2 * NUM_IDS / 4; i += THREADS) z[i] = zero4;
    }

    // hot table rows (a=0,1 cover ~97% of lookups); S = T0+T1 is the common row sum
    const float4 t0r = __ldg(&gT4[0 * 32 + lane]);
    const float4 t1r = __ldg(&gT4[1 * 32 + lane]);
    float4 S;
    S.x = t0r.x + t1r.x; S.y = t0r.y + t1r.y;
    S.z = t0r.z + t1r.z; S.w = t0r.w + t1r.w;
    __syncthreads();

    // ---- histogram: each thread owns one neighbor element ----
    const int b    = base + p;
    const int lst  = (h < L) ? 0 : 1;                       // 0 = src list, 1 = dst list
    const int my_x = (h < L) ? __ldg(&src_nb[b * L + h])
                             : __ldg(&dst_nb[b * L + (h - L)]);
    atomicAdd(&s_cnt[p][lst][my_x], 1);
    __syncthreads();

    // ---- counts + dict-mutation overrides (exact reference semantics) ----
    {
        const int sid = __ldg(&src_ids[b]);
        const int did = __ldg(&dst_ids[b]);
        const int cd  = s_cnt[p][1][sid];                   // count(src_id in dst list)
        const int cs  = s_cnt[p][0][did];                   // count(dst_id in src list)
        const bool same   = (sid == did);
        const bool in_dst = (cd > 0);                       // srcid_in_dst
        const bool cond2  = (cs > 0) || (same && in_dst);
        const int  v2     = (same && in_dst) ? cd : cs;

        const int c_self  = s_cnt[p][lst][my_x];            // count in own list
        const int c_other = s_cnt[p][lst ^ 1][my_x];        // count in other list
        int a0, a1;
        if (h < L) {
            a0 = c_self;                                    // c_src
            a1 = (my_x == did && cond2)  ? v2 : c_other;    // src_col1
        } else {
            a0 = (my_x == sid && in_dst) ? cd : c_other;    // dst_col0
            a1 = c_self;                                    // c_dst
        }
        s_a[p][h] = a0 | (a1 << 8);
    }
    __syncthreads();

    // ---- barrier-free streaming store: each warp owns 32 contiguous rows ----
    // warp w: pp = w>>2 (batch), isdst = (w>>1)&1, r0 = (w&1)*32
    {
        const int pp    = wrp >> 2;
        const int isdst = (wrp >> 1) & 1;
        const int r0    = (wrp & 1) * 32;
        const int bb    = base + pp;
        float4* ptr = (float4*)(out + (isdst ? half : 0)
                                + (size_t)bb * L * D + r0 * D) + lane;
        const int* sa = &s_a[pp][isdst * L + r0];

        #pragma unroll
        for (int i = 0; i < 32; ++i) {
            const int packed = sa[i];                        // warp-uniform broadcast
            float4 o;
            if (packed == 1 || packed == 256) {              // (1,0) or (0,1): ~88%
                o = S;
            } else {                                         // warp-uniform rare path
                const int a0 = packed & 0xFF;
                const int a1 = packed >> 8;
                const float4 ta = __ldg(&gT4[a0 * 32 + lane]);
                const float4 tb = __ldg(&gT4[a1 * 32 + lane]);
                o.x = ta.x + tb.x; o.y = ta.y + tb.y;
                o.z = ta.z + tb.z; o.w = ta.w + tb.w;
            }
            __stcs(ptr + i * (D / 4), o);
        }
    }
}

extern "C" void kernel_launch(void* const* d_in, const int* in_sizes, int n_in,
                              void* d_out, int out_size)
{
    const int*   src_ids = (const int*)  d_in[0];
    const int*   dst_ids = (const int*)  d_in[1];
    const int*   src_nb  = (const int*)  d_in[2];
    const int*   dst_nb  = (const int*)  d_in[3];
    const float* W1      = (const float*)d_in[4];
    const float* b1      = (const float*)d_in[5];
    const float* W2      = (const float*)d_in[6];
    const float* b2      = (const float*)d_in[7];
    float*       out     = (float*)d_out;

    build_table_kernel<<<TMAX, D>>>(W1, b1, W2, b2);
    nif_encoder_kernel<<<GRID, THREADS>>>(src_ids, dst_ids, src_nb, dst_nb, out);
}

// round 7
// speedup vs baseline: 1.1345x; 1.0936x over previous
#include <cuda_runtime.h>

#define NB 4096
#define L 64
#define D 128
#define TMAX 65            // counts are in [0, 64]
#define NUM_IDS 1000
#define NWORDS 250         // 1000 ids, 4 byte-counters per word
#define BPB 2              // batches per block (one per half-block)
#define GRID (NB / BPB)    // 2048 blocks
#define THREADS 256

// Lookup table: T[a][e] = sum_d relu(a*W1[d]+b1[d]) * W2[d][e] + b2[e]
__device__ float g_T[TMAX * D];
__device__ unsigned int g_done = 0;   // monotonic; >=65 once table built (replays: builders rewrite identical values)

__global__ __launch_bounds__(THREADS) void nif_fused_kernel(
    const int* __restrict__ src_ids, const int* __restrict__ dst_ids,
    const int* __restrict__ src_nb,  const int* __restrict__ dst_nb,
    const float* __restrict__ W1, const float* __restrict__ b1,
    const float* __restrict__ W2, const float* __restrict__ b2,
    float* __restrict__ out)
{
    __shared__ unsigned int s_cnt[BPB][2][NWORDS];  // byte-packed counts, 4 KB
    __shared__ int   s_a[BPB][2 * L];               // packed a0 | (a1<<8)
    __shared__ float s_h[D];                        // builder scratch

    const int tid  = threadIdx.x;
    const int lane = tid & 31;
    const int wrp  = tid >> 5;               // 0..7
    const int p    = tid >> 7;               // which batch of this block (0/1)
    const int h    = tid & 127;              // thread-in-batch (one neighbor elem)
    const int base = blockIdx.x * BPB;
    const size_t half = (size_t)NB * L * D;
    const float4* gT4 = (const float4*)g_T;  // [TMAX][32] float4

    // ================= table-builder role: blocks 0..64 =================
    if (blockIdx.x < TMAX) {
        const int a = blockIdx.x;
        if (tid < D) s_h[tid] = fmaxf((float)a * W1[tid] + b1[tid], 0.0f);
        __syncthreads();
        if (tid < D) {
            float acc = b2[tid];
            #pragma unroll 8
            for (int d = 0; d < D; ++d)
                acc = fmaf(s_h[d], W2[d * D + tid], acc);
            g_T[a * D + tid] = acc;
        }
        __syncthreads();
        if (tid == 0) {
            __threadfence();                          // release table writes
            atomicAdd(&g_done, 1u);
        }
    }

    // ================= histogram phase (table-independent) ===============
    {
        unsigned int* z = &s_cnt[0][0][0];
        #pragma unroll
        for (int i = tid; i < BPB * 2 * NWORDS; i += THREADS) z[i] = 0u;
    }
    __syncthreads();

    const int b    = base + p;
    const int lst  = (h < L) ? 0 : 1;                       // 0 = src list, 1 = dst list
    const int my_x = (h < L) ? __ldg(&src_nb[b * L + h])
                             : __ldg(&dst_nb[b * L + (h - L)]);
    atomicAdd(&s_cnt[p][lst][my_x >> 2], 1u << ((my_x & 3) * 8));
    __syncthreads();

    // ---- counts + dict-mutation overrides (exact reference semantics) ----
    {
        const int sid = __ldg(&src_ids[b]);
        const int did = __ldg(&dst_ids[b]);
        const int cd  = (s_cnt[p][1][sid >> 2] >> ((sid & 3) * 8)) & 0xFF;  // src_id in dst list
        const int cs  = (s_cnt[p][0][did >> 2] >> ((did & 3) * 8)) & 0xFF;  // dst_id in src list
        const bool same   = (sid == did);
        const bool in_dst = (cd > 0);                       // srcid_in_dst
        const bool cond2  = (cs > 0) || (same && in_dst);
        const int  v2     = (same && in_dst) ? cd : cs;

        const int c_self  = (s_cnt[p][lst][my_x >> 2]     >> ((my_x & 3) * 8)) & 0xFF;
        const int c_other = (s_cnt[p][lst ^ 1][my_x >> 2] >> ((my_x & 3) * 8)) & 0xFF;
        int a0, a1;
        if (h < L) {
            a0 = c_self;                                    // c_src
            a1 = (my_x == did && cond2)  ? v2 : c_other;    // src_col1
        } else {
            a0 = (my_x == sid && in_dst) ? cd : c_other;    // dst_col0
            a1 = c_self;                                    // c_dst
        }
        s_a[p][h] = a0 | (a1 << 8);
    }

    // ================= wait for the table (usually already done) =========
    if (tid == 0) {
        unsigned int v;
        do {
            asm volatile("ld.acquire.gpu.u32 %0, [%1];" : "=r"(v) : "l"(&g_done) : "memory");
        } while (v < TMAX);
    }
    __syncthreads();

    // hot table rows (a=0,1 cover ~97%); S = T0+T1 is the common row sum
    const float4 t0r = __ldg(&gT4[0 * 32 + lane]);
    const float4 t1r = __ldg(&gT4[1 * 32 + lane]);
    float4 S;
    S.x = t0r.x + t1r.x; S.y = t0r.y + t1r.y;
    S.z = t0r.z + t1r.z; S.w = t0r.w + t1r.w;

    // ================= barrier-free streaming store ======================
    // warp w: pp = w>>2 (batch), isdst = (w>>1)&1, r0 = (w&1)*32 -> 32 contiguous rows
    {
        const int pp    = wrp >> 2;
        const int isdst = (wrp >> 1) & 1;
        const int r0    = (wrp & 1) * 32;
        const int bb    = base + pp;
        float4* ptr = (float4*)(out + (isdst ? half : 0)
                                + (size_t)bb * L * D + r0 * D) + lane;
        const int* sa = &s_a[pp][isdst * L + r0];

        #pragma unroll
        for (int i = 0; i < 32; ++i) {
            const int packed = sa[i];                        // warp-uniform broadcast
            float4 o;
            if (packed == 1 || packed == 256) {              // (1,0) or (0,1): ~88%
                o = S;
            } else {                                         // warp-uniform rare path
                const int a0 = packed & 0xFF;
                const int a1 = packed >> 8;
                const float4 ta = __ldg(&gT4[a0 * 32 + lane]);
                const float4 tb = __ldg(&gT4[a1 * 32 + lane]);
                o.x = ta.x + tb.x; o.y = ta.y + tb.y;
                o.z = ta.z + tb.z; o.w = ta.w + tb.w;
            }
            __stcs(ptr + i * (D / 4), o);
        }
    }
}

extern "C" void kernel_launch(void* const* d_in, const int* in_sizes, int n_in,
                              void* d_out, int out_size)
{
    const int*   src_ids = (const int*)  d_in[0];
    const int*   dst_ids = (const int*)  d_in[1];
    const int*   src_nb  = (const int*)  d_in[2];
    const int*   dst_nb  = (const int*)  d_in[3];
    const float* W1      = (const float*)d_in[4];
    const float* b1      = (const float*)d_in[5];
    const float* W2      = (const float*)d_in[6];
    const float* b2      = (const float*)d_in[7];
    float*       out     = (float*)d_out;

    nif_fused_kernel<<<GRID, THREADS>>>(src_ids, dst_ids, src_nb, dst_nb,
                                        W1, b1, W2, b2, out);
}